// round 5
// baseline (speedup 1.0000x reference)
#include <cuda_runtime.h>
#include <cuda_bf16.h>
#include <cstdint>
#include <math.h>

// ---------------------------------------------------------------------------
// Problem constants (fixed: N=4096, D=1024)
#define NN     4096
#define DD     1024
#define N2     8192
#define INV_T  (1.0f / 0.07f)

#define TILE   128
#define NT     (N2 / TILE)            // 64 row/col blocks
#define NTILES (NT * (NT + 1) / 2)    // 2080 upper-triangle tiles
#define KCHUNK 64                     // bf16 per K chunk
#define NCHUNK (DD / KCHUNK)          // 16

// SMEM (dynamic): per stage 36864 B = A[128][72]bf16 (18432) + B same.
#define STAGE_B   36864
#define SM_BOFF   18432
#define SM_RPART  73728               // 8 warps x 64 rows x f32 = 2048 B
#define SM_CPART  75776               // 2 x 128 x f32 = 1024 B
#define SM_BYTES  76800

// ---------------------------------------------------------------------------
__device__ __nv_bfloat16 g_zb[(size_t)N2 * DD];   // normalized rows, bf16
__device__ float g_pos[NN];
__device__ float g_partial[(size_t)NT * N2];      // [slot][row] exp-sum parts
__device__ float g_rowval[N2];

// ---------------------------------------------------------------------------
__device__ __forceinline__ uint32_t smem_u32(const void* p) {
    uint32_t a;
    asm("{ .reg .u64 t; cvta.to.shared.u64 t, %1; cvt.u32.u64 %0, t; }"
        : "=r"(a) : "l"(p));
    return a;
}
__device__ __forceinline__ void cp16(uint32_t dst, const void* src) {
    asm volatile("cp.async.cg.shared.global [%0], [%1], 16;" :: "r"(dst), "l"(src));
}
__device__ __forceinline__ void ldsm_x4(uint32_t a, uint32_t& r0, uint32_t& r1,
                                        uint32_t& r2, uint32_t& r3) {
    asm volatile("ldmatrix.sync.aligned.m8n8.x4.shared.b16 {%0,%1,%2,%3}, [%4];"
                 : "=r"(r0), "=r"(r1), "=r"(r2), "=r"(r3) : "r"(a));
}
__device__ __forceinline__ void mma16816(float* c, uint32_t a0, uint32_t a1,
                                         uint32_t a2, uint32_t a3,
                                         uint32_t b0, uint32_t b1) {
    asm volatile("mma.sync.aligned.m16n8k16.row.col.f32.bf16.bf16.f32 "
                 "{%0,%1,%2,%3}, {%4,%5,%6,%7}, {%8,%9}, {%0,%1,%2,%3};"
                 : "+f"(c[0]), "+f"(c[1]), "+f"(c[2]), "+f"(c[3])
                 : "r"(a0), "r"(a1), "r"(a2), "r"(a3), "r"(b0), "r"(b1));
}

__device__ __forceinline__ float block_reduce_sum(float v) {
    __shared__ float sh[32];
    int lane = threadIdx.x & 31, w = threadIdx.x >> 5;
    #pragma unroll
    for (int o = 16; o; o >>= 1) v += __shfl_down_sync(0xffffffffu, v, o);
    if (lane == 0) sh[w] = v;
    __syncthreads();
    v = (threadIdx.x < (blockDim.x >> 5)) ? sh[threadIdx.x] : 0.0f;
    if (w == 0) {
        #pragma unroll
        for (int o = 16; o; o >>= 1) v += __shfl_down_sync(0xffffffffu, v, o);
    }
    return v;
}

// ---------------------------------------------------------------------------
// Kernel 1 (fused): one block per pair i. Reads l1_i and l2_i once; computes
// both L2 norms + fp32 dot, writes both bf16 normalized rows + g_pos[i].
__global__ void prep_kernel(const float* __restrict__ l1,
                            const float* __restrict__ l2) {
    const int i = blockIdx.x;
    const float* a = l1 + (size_t)i * DD;
    const float* b = l2 + (size_t)i * DD;
    float va[4], vb[4], s1 = 0.0f, s2 = 0.0f, dt = 0.0f;
    #pragma unroll
    for (int j = 0; j < 4; j++) {
        int k = threadIdx.x + j * 256;
        va[j] = a[k]; vb[j] = b[k];
        s1 += va[j] * va[j];
        s2 += vb[j] * vb[j];
        dt += va[j] * vb[j];
    }
    __shared__ float sh1, sh2, shd;
    float t;
    t = block_reduce_sum(s1); if (threadIdx.x == 0) sh1 = t;
    __syncthreads();
    t = block_reduce_sum(s2); if (threadIdx.x == 0) sh2 = t;
    __syncthreads();
    t = block_reduce_sum(dt); if (threadIdx.x == 0) shd = t;
    __syncthreads();
    const float i1 = rsqrtf(sh1), i2 = rsqrtf(sh2);
    if (threadIdx.x == 0) g_pos[i] = shd * i1 * i2;
    __nv_bfloat16* d1 = g_zb + (size_t)i * DD;
    __nv_bfloat16* d2 = g_zb + (size_t)(i + NN) * DD;
    #pragma unroll
    for (int j = 0; j < 4; j++) {
        int k = threadIdx.x + j * 256;
        d1[k] = __float2bfloat16(va[j] * i1);
        d2[k] = __float2bfloat16(vb[j] * i2);
    }
}

// ---------------------------------------------------------------------------
// Kernel 2: bf16 mma.sync GEMM over upper-triangle 128x128 tiles, fused
// exp + row/col exp-sum reduction. Tile (bi,bj), bi<=bj:
//   row-sums -> g_partial[bj][bi*128 + r];  col-sums -> g_partial[bi][bj*128+c]
// Each slot written by exactly one block -> deterministic.
__global__ void __launch_bounds__(256, 2) simexp_mma_kernel() {
    extern __shared__ char smem[];
    const uint32_t sb = smem_u32(smem);
    const int tid = threadIdx.x, wid = tid >> 5, lane = tid & 31;
    const int wr = wid >> 2, wc = wid & 3;    // warp grid 2 x 4 -> 64 x 32 tiles

    // decode upper-triangle tile index
    int idx = blockIdx.x, bi = 0;
    while (idx >= NT - bi) { idx -= NT - bi; bi++; }
    const int bj = bi + idx;

    const __nv_bfloat16* Abase = g_zb + (size_t)bi * TILE * DD;
    const __nv_bfloat16* Bbase = g_zb + (size_t)bj * TILE * DD;

    // loader mapping: 256 thr x 16B granules; 4 row-steps cover 128 rows
    const int lr = tid >> 3;                  // base row (0..31)
    const int lg = tid & 7;                   // granule (16B = 8 halves)
    const uint32_t ldst = (uint32_t)lr * 144 + lg * 16;

    // ldmatrix row offsets (stage-relative, bytes)
    uint32_t a_off[4], b_off[2];
    #pragma unroll
    for (int mt = 0; mt < 4; mt++)
        a_off[mt] = (uint32_t)(wr * 64 + mt * 16 + (lane & 15)) * 144 + (lane >> 4) * 16;
    #pragma unroll
    for (int np = 0; np < 2; np++)
        b_off[np] = SM_BOFF + (uint32_t)(wc * 32 + np * 16 + (lane & 15)) * 144
                  + (lane >> 4) * 16;

    float acc[4][4][4];
    #pragma unroll
    for (int mt = 0; mt < 4; mt++)
        #pragma unroll
        for (int nt = 0; nt < 4; nt++)
            #pragma unroll
            for (int r = 0; r < 4; r++) acc[mt][nt][r] = 0.0f;

    // prologue: load chunk 0 -> stage 0
    #pragma unroll
    for (int i = 0; i < 4; i++) {
        int r = lr + i * 32;
        uint32_t d = ldst + (uint32_t)i * 32 * 144;
        cp16(sb + d,            Abase + (size_t)r * DD + lg * 8);
        cp16(sb + SM_BOFF + d,  Bbase + (size_t)r * DD + lg * 8);
    }
    asm volatile("cp.async.commit_group;" ::: "memory");

    for (int c = 0; c < NCHUNK; c++) {
        if (c + 1 < NCHUNK) {
            const uint32_t s1 = sb + ((c + 1) & 1) * STAGE_B;
            #pragma unroll
            for (int i = 0; i < 4; i++) {
                int r = lr + i * 32;
                uint32_t d = ldst + (uint32_t)i * 32 * 144;
                cp16(s1 + d,           Abase + (size_t)r * DD + (c + 1) * KCHUNK + lg * 8);
                cp16(s1 + SM_BOFF + d, Bbase + (size_t)r * DD + (c + 1) * KCHUNK + lg * 8);
            }
            asm volatile("cp.async.commit_group;" ::: "memory");
            asm volatile("cp.async.wait_group 1;" ::: "memory");
        } else {
            asm volatile("cp.async.wait_group 0;" ::: "memory");
        }
        __syncthreads();

        const uint32_t s0 = sb + (c & 1) * STAGE_B;
        #pragma unroll
        for (int ks = 0; ks < 4; ks++) {
            uint32_t a[4][4], q[2][4];
            #pragma unroll
            for (int mt = 0; mt < 4; mt++)
                ldsm_x4(s0 + a_off[mt] + ks * 32,
                        a[mt][0], a[mt][1], a[mt][2], a[mt][3]);
            #pragma unroll
            for (int np = 0; np < 2; np++)
                ldsm_x4(s0 + b_off[np] + ks * 32,
                        q[np][0], q[np][1], q[np][2], q[np][3]);
            #pragma unroll
            for (int mt = 0; mt < 4; mt++) {
                mma16816(acc[mt][0], a[mt][0], a[mt][1], a[mt][2], a[mt][3],
                         q[0][0], q[0][2]);
                mma16816(acc[mt][1], a[mt][0], a[mt][1], a[mt][2], a[mt][3],
                         q[0][1], q[0][3]);
                mma16816(acc[mt][2], a[mt][0], a[mt][1], a[mt][2], a[mt][3],
                         q[1][0], q[1][2]);
                mma16816(acc[mt][3], a[mt][0], a[mt][1], a[mt][2], a[mt][3],
                         q[1][1], q[1][3]);
            }
        }
        __syncthreads();
    }

    // ---------------- epilogue: exp + exact diag mask + row/col sums -------
    // acc[mt][nt] lane layout: rows mt*16 + (lane>>2) (+8), cols nt*8 + 2*(lane&3) (+1)
    const int lrow0 = wr * 64 + (lane >> 2);
    const int lcol0 = wc * 32 + 2 * (lane & 3);
    const bool diag = (bi == bj);
    float rowp[4][2], colp[4][2];
    #pragma unroll
    for (int t = 0; t < 4; t++) { rowp[t][0] = rowp[t][1] = colp[t][0] = colp[t][1] = 0.0f; }

    #pragma unroll
    for (int mt = 0; mt < 4; mt++)
        #pragma unroll
        for (int nt = 0; nt < 4; nt++) {
            float e0 = __expf(acc[mt][nt][0] * INV_T);
            float e1 = __expf(acc[mt][nt][1] * INV_T);
            float e2 = __expf(acc[mt][nt][2] * INV_T);
            float e3 = __expf(acc[mt][nt][3] * INV_T);
            if (diag) {
                int r0 = lrow0 + mt * 16, c0 = lcol0 + nt * 8;
                if (r0 == c0)         e0 = 0.0f;
                if (r0 == c0 + 1)     e1 = 0.0f;
                if (r0 + 8 == c0)     e2 = 0.0f;
                if (r0 + 8 == c0 + 1) e3 = 0.0f;
            }
            rowp[mt][0] += e0 + e1;  rowp[mt][1] += e2 + e3;
            colp[nt][0] += e0 + e2;  colp[nt][1] += e1 + e3;
        }

    // rows: lanes within a quad (same lane>>2) share rows
    #pragma unroll
    for (int off = 1; off <= 2; off <<= 1)
        #pragma unroll
        for (int mt = 0; mt < 4; mt++) {
            rowp[mt][0] += __shfl_xor_sync(0xffffffffu, rowp[mt][0], off);
            rowp[mt][1] += __shfl_xor_sync(0xffffffffu, rowp[mt][1], off);
        }
    // cols: lanes with same (lane&3) share columns
    #pragma unroll
    for (int off = 4; off <= 16; off <<= 1)
        #pragma unroll
        for (int nt = 0; nt < 4; nt++) {
            colp[nt][0] += __shfl_xor_sync(0xffffffffu, colp[nt][0], off);
            colp[nt][1] += __shfl_xor_sync(0xffffffffu, colp[nt][1], off);
        }

    float* rpart = (float*)(smem + SM_RPART);   // [8 warps][64 rows]
    float* cpart = (float*)(smem + SM_CPART);   // [2 wr][128 cols]
    if ((lane & 3) == 0) {
        int g = lane >> 2;
        #pragma unroll
        for (int mt = 0; mt < 4; mt++) {
            rpart[wid * 64 + mt * 16 + g]     = rowp[mt][0];
            rpart[wid * 64 + mt * 16 + g + 8] = rowp[mt][1];
        }
    }
    if (lane < 4) {
        #pragma unroll
        for (int nt = 0; nt < 4; nt++) {
            cpart[wr * 128 + wc * 32 + nt * 8 + 2 * lane]     = colp[nt][0];
            cpart[wr * 128 + wc * 32 + nt * 8 + 2 * lane + 1] = colp[nt][1];
        }
    }
    __syncthreads();
    if (tid < 128) {
        int hw = tid >> 6;    // which wr half
        float rs = rpart[(hw * 4 + 0) * 64 + (tid & 63)]
                 + rpart[(hw * 4 + 1) * 64 + (tid & 63)]
                 + rpart[(hw * 4 + 2) * 64 + (tid & 63)]
                 + rpart[(hw * 4 + 3) * 64 + (tid & 63)];
        g_partial[(size_t)bj * N2 + bi * TILE + tid] = rs;
        if (bi != bj) {
            float cs = cpart[tid] + cpart[128 + tid];
            g_partial[(size_t)bi * N2 + bj * TILE + tid] = cs;
        }
    }
}

// ---------------------------------------------------------------------------
// Kernel 3: per-row lse - pos/T.
__global__ void rowval_kernel() {
    int r = blockIdx.x * 256 + threadIdx.x;
    float s = 0.0f;
    #pragma unroll 4
    for (int t = 0; t < NT; t++) s += g_partial[(size_t)t * N2 + r];
    g_rowval[r] = logf(s) - g_pos[r & (NN - 1)] * INV_T;
}

// Kernel 4: mean -> scalar loss.
__global__ void final_kernel(float* __restrict__ out) {
    float s = 0.0f;
    for (int i = threadIdx.x; i < N2; i += 256) s += g_rowval[i];
    float t = block_reduce_sum(s);
    if (threadIdx.x == 0) out[0] = t * (1.0f / (float)N2);
}

// ---------------------------------------------------------------------------
extern "C" void kernel_launch(void* const* d_in, const int* in_sizes, int n_in,
                              void* d_out, int out_size) {
    const float* l1 = (const float*)d_in[0];
    const float* l2 = (const float*)d_in[1];
    float* out = (float*)d_out;
    (void)in_sizes; (void)n_in; (void)out_size;

    cudaFuncSetAttribute(simexp_mma_kernel,
                         cudaFuncAttributeMaxDynamicSharedMemorySize, SM_BYTES);

    prep_kernel<<<NN, 256>>>(l1, l2);
    simexp_mma_kernel<<<NTILES, 256, SM_BYTES>>>();
    rowval_kernel<<<N2 / 256, 256>>>();
    final_kernel<<<1, 256>>>(out);
}